// round 12
// baseline (speedup 1.0000x reference)
#include <cuda_runtime.h>

#define EPSLN 1e-5f
#define RS 68   // smem row stride in floats (4g+t bank pattern -> conflict-free)

__device__ __forceinline__ unsigned cvt_tf32(float x) {
    unsigned r; asm("cvt.rna.tf32.f32 %0, %1;" : "=r"(r) : "f"(x)); return r;
}

#define MMA_TF32(d, a, b)                                                          \
    asm volatile(                                                                  \
        "mma.sync.aligned.m16n8k8.row.col.f32.tf32.tf32.f32 "                      \
        "{%0,%1,%2,%3},{%4,%5,%6,%7},{%8,%9},{%0,%1,%2,%3};"                       \
        : "+f"(d[0]), "+f"(d[1]), "+f"(d[2]), "+f"(d[3])                           \
        : "r"(a[0]), "r"(a[1]), "r"(a[2]), "r"(a[3]), "r"(b[0]), "r"(b[1]))

// Named barrier over the 64 threads (2 warps) serving one batch
#define BARX(id) asm volatile("bar.sync %0, 64;" :: "r"(id) : "memory")

#define CP_ASYNC16(dst_u32, src_ptr)                                               \
    asm volatile("cp.async.cg.shared.global [%0], [%1], 16;"                       \
                 :: "r"(dst_u32), "l"(src_ptr))

__global__ __launch_bounds__(256, 3) void gat_kernel(
    const float* __restrict__ nodes,
    const float* __restrict__ edges,
    const float* __restrict__ Ww,
    const float* __restrict__ Wbias,
    const float* __restrict__ Wew,
    const float* __restrict__ attw,
    const float* __restrict__ gamma,
    const float* __restrict__ beta,
    float* __restrict__ out)
{
    __shared__ float  sN[4][33 * RS];        // nodes, raw fp32 (MMA truncates to tf32)
    __shared__ uint2  sB[8 * 8 * 32];        // weight fragments (16 KB), built in-CTA
    __shared__ float  sE[16];                // We_w @ attn_w[128:192]
    __shared__ float2 sSum[4][2][33];        // (sum, sumsq) per row/half
    __shared__ float  sScore[4][2][32];      // attention scores rows 1..32
    __shared__ float  sAttn[4][32];
    __shared__ float2 sT[4][2];              // target LN partials per half

    const int tid  = threadIdx.x;
    const int lane = tid & 31;
    const int warp = tid >> 5;
    const int bl   = warp >> 1;     // batch within CTA (0..3)
    const int half = warp & 1;      // column half (32 cols)
    const int t    = lane & 3;      // threadID-in-group
    const int g    = lane >> 2;     // groupID
    const long long b = (long long)blockIdx.x * 4 + bl;
    const int barid = bl + 1;

    // ---- stage nodes via cp.async (issued first; everything below hides under it) ----
    const float4* srcAll = (const float4*)(nodes + (long long)blockIdx.x * 4 * 2112);
#pragma unroll
    for (int qq = 0; qq < 9; ++qq) {
        int q = tid + qq * 256;
        if (q < 2112) {
            int bb = q / 528;
            int ql = q - bb * 528;
            int r  = ql >> 4, i4 = ql & 15;
            unsigned dst = (unsigned)__cvta_generic_to_shared(&sN[bb][r * RS + i4 * 4]);
            CP_ASYNC16(dst, srcAll + q);
        }
    }
    asm volatile("cp.async.commit_group;" ::: "memory");

    // ---- build B fragments in-CTA from Ww (16 KB, L2-resident across grid) ----
    // B fragment for m16n8k8.row.col: b0 = W[ks*8+tt][nt*8+gg], b1 = W[ks*8+tt+4][nt*8+gg]
#pragma unroll
    for (int k = 0; k < 8; ++k) {
        int idx = tid + k * 256;
        int ln  = idx & 31;
        int nt  = (idx >> 5) & 7;
        int ks  = idx >> 8;
        int tt = ln & 3, gg = ln >> 2;
        uint2 v;
        v.x = cvt_tf32(__ldg(&Ww[(ks * 8 + tt)     * 64 + nt * 8 + gg]));
        v.y = cvt_tf32(__ldg(&Ww[(ks * 8 + tt + 4) * 64 + nt * 8 + gg]));
        sB[idx] = v;
    }

    // ---- edge-score projection vector (16 threads, serial dots; hidden) ----
    if (tid < 16) {
        float se = 0.f;
#pragma unroll 8
        for (int o = 0; o < 64; ++o) se += __ldg(&Wew[tid * 64 + o]) * __ldg(&attw[128 + o]);
        sE[tid] = se;
    }

    // ---- early edge loads (registers; consumed after the sync) ----
    float4 ev0, ev1, ev2, ev3;
    if (half == 0) {
        const float4* er = (const float4*)(edges + (b * 32 + lane) * 16);
        ev0 = __ldg(er); ev1 = __ldg(er + 1); ev2 = __ldg(er + 2); ev3 = __ldg(er + 3);
    }

    asm volatile("cp.async.wait_group 0;" ::: "memory");
    __syncthreads();  // staging + sB + sE complete (CTA-wide, once)

    // ---- edge score term (half==0 warps, lane = neighbor k) ----
    float ek = 0.f;
    if (half == 0) {
        ek  = ev0.x * sE[0]  + ev0.y * sE[1]  + ev0.z * sE[2]  + ev0.w * sE[3];
        ek += ev1.x * sE[4]  + ev1.y * sE[5]  + ev1.z * sE[6]  + ev1.w * sE[7];
        ek += ev2.x * sE[8]  + ev2.y * sE[9]  + ev2.z * sE[10] + ev2.w * sE[11];
        ek += ev3.x * sE[12] + ev3.y * sE[13] + ev3.z * sE[14] + ev3.w * sE[15];
    }

    // ---- tensor-core GEMM: 3 m16 tiles x 4 n8 tiles (this warp's half) ----
    // A operands fed as raw fp32 bits (HW reads top 19 bits = tf32 truncation).
    const unsigned* sNb = (const unsigned*)sN[bl];
    float d[3][4][4];
#pragma unroll
    for (int m = 0; m < 3; ++m)
#pragma unroll
        for (int j = 0; j < 4; ++j)
#pragma unroll
            for (int c = 0; c < 4; ++c) d[m][j][c] = 0.f;

#pragma unroll
    for (int ks = 0; ks < 8; ++ks) {
        unsigned bb[4][2];
#pragma unroll
        for (int j = 0; j < 4; ++j) {
            uint2 v = sB[(ks * 8 + half * 4 + j) * 32 + lane];
            bb[j][0] = v.x; bb[j][1] = v.y;
        }
        unsigned aa[3][4];
#pragma unroll
        for (int m = 0; m < 2; ++m) {
            int base = (m * 16 + g) * RS + ks * 8 + t;
            aa[m][0] = sNb[base];
            aa[m][1] = sNb[base + 8 * RS];
            aa[m][2] = sNb[base + 4];
            aa[m][3] = sNb[base + 8 * RS + 4];
        }
        if (g == 0) {   // m-tile 2: only row 32 real
            int base = 32 * RS + ks * 8 + t;
            aa[2][0] = sNb[base];
            aa[2][2] = sNb[base + 4];
        } else { aa[2][0] = 0u; aa[2][2] = 0u; }
        aa[2][1] = 0u; aa[2][3] = 0u;

#pragma unroll
        for (int m = 0; m < 3; ++m)
#pragma unroll
            for (int j = 0; j < 4; ++j)
                MMA_TF32(d[m][j], aa[m], bb[j]);
    }

    // ---- epilogue params (post-GEMM to keep mainloop registers lean) ----
    const int col0 = half * 32 + 2 * t;
    float2 wb2[4], aw2[4], g2[4], be2[4];
#pragma unroll
    for (int j = 0; j < 4; ++j) {
        wb2[j] = *(const float2*)(Wbias + col0 + j * 8);
        aw2[j] = *(const float2*)(attw + 64 + col0 + j * 8);
        g2[j]  = *(const float2*)(gamma + col0 + j * 8);
        be2[j] = *(const float2*)(beta  + col0 + j * 8);
    }

    // ---- add bias; per-row stats (sum, sumsq, score) ----
#pragma unroll
    for (int m = 0; m < 3; ++m)
#pragma unroll
        for (int j = 0; j < 4; ++j) {
            d[m][j][0] += wb2[j].x; d[m][j][1] += wb2[j].y;
            d[m][j][2] += wb2[j].x; d[m][j][3] += wb2[j].y;
        }

    float sm[3][2], s2[3][2], sc[3][2];
#pragma unroll
    for (int m = 0; m < 3; ++m)
#pragma unroll
        for (int rh = 0; rh < 2; ++rh) {
            float a = 0.f, q = 0.f, s = 0.f;
#pragma unroll
            for (int j = 0; j < 4; ++j) {
                float h0 = d[m][j][rh * 2], h1 = d[m][j][rh * 2 + 1];
                a += h0 + h1;
                q = fmaf(h0, h0, fmaf(h1, h1, q));
                s = fmaf(h0, aw2[j].x, fmaf(h1, aw2[j].y, s));
            }
#pragma unroll
            for (int dl = 1; dl <= 2; dl <<= 1) {
                a += __shfl_xor_sync(0xffffffffu, a, dl);
                q += __shfl_xor_sync(0xffffffffu, q, dl);
                s += __shfl_xor_sync(0xffffffffu, s, dl);
            }
            sm[m][rh] = a; s2[m][rh] = q; sc[m][rh] = s;
        }
    if (t == 0) {
        sSum[bl][half][g]      = make_float2(sm[0][0], s2[0][0]);
        sSum[bl][half][g + 8]  = make_float2(sm[0][1], s2[0][1]);
        sSum[bl][half][g + 16] = make_float2(sm[1][0], s2[1][0]);
        sSum[bl][half][g + 24] = make_float2(sm[1][1], s2[1][1]);
        if (g > 0) sScore[bl][half][g - 1] = sc[0][0];
        sScore[bl][half][g + 7]  = sc[0][1];   // row g+8
        sScore[bl][half][g + 15] = sc[1][0];   // row 16+g
        sScore[bl][half][g + 23] = sc[1][1];   // row 24+g
        if (g == 0) {
            sSum[bl][half][32]   = make_float2(sm[2][0], s2[2][0]);
            sScore[bl][half][31] = sc[2][0];   // row 32
        }
    }
    BARX(barid);   // only this batch's 2 warps

    // ---- layernorm + store for neighbor rows (1..32) ----
    float* gO = out + b * 2112;
#pragma unroll
    for (int m = 0; m < 3; ++m)
#pragma unroll
        for (int rh = 0; rh < 2; ++rh) {
            int row = m * 16 + g + rh * 8;
            bool valid = (row >= 1) && (row <= 32) && !(m == 2 && !(g == 0 && rh == 0));
            if (valid) {
                float2 u0 = sSum[bl][0][row];
                float2 u1 = sSum[bl][1][row];
                float mu  = (u0.x + u1.x) * (1.f / 64.f);
                float var = fmaf(u0.y + u1.y, 1.f / 64.f, -mu * mu);
                float ri  = rsqrtf(var + EPSLN);
#pragma unroll
                for (int j = 0; j < 4; ++j) {
                    float2 o;
                    o.x = fmaf((d[m][j][rh * 2]     - mu) * ri, g2[j].x, be2[j].x);
                    o.y = fmaf((d[m][j][rh * 2 + 1] - mu) * ri, g2[j].y, be2[j].y);
                    *(float2*)(gO + row * 64 + col0 + j * 8) = o;
                }
            }
        }

    // ---- softmax over 32 neighbor scores (half==0 warp of each batch) ----
    if (half == 0) {
        float s = sScore[bl][0][lane] + sScore[bl][1][lane] + ek;
        float mx = s;
#pragma unroll
        for (int dl = 16; dl > 0; dl >>= 1) mx = fmaxf(mx, __shfl_xor_sync(0xffffffffu, mx, dl));
        float p = __expf(s - mx);
        float tot = p;
#pragma unroll
        for (int dl = 16; dl > 0; dl >>= 1) tot += __shfl_xor_sync(0xffffffffu, tot, dl);
        sAttn[bl][lane] = p / tot;
    }
    BARX(barid);

    // ---- messages: msg[col] = sum_k attn_k * h_k[col] ----
    float aA = (g > 0) ? sAttn[bl][g - 1] : 0.f;   // row g
    float aB = sAttn[bl][g + 7];                    // row g+8
    float aC = sAttn[bl][g + 15];                   // row 16+g
    float aD = sAttn[bl][g + 23];                   // row 24+g
    float aE = (g == 0) ? sAttn[bl][31] : 0.f;      // row 32

    float pm[4][2];
#pragma unroll
    for (int j = 0; j < 4; ++j)
#pragma unroll
        for (int c = 0; c < 2; ++c) {
            float v = aA * d[0][j][c] + aB * d[0][j][2 + c]
                    + aC * d[1][j][c] + aD * d[1][j][2 + c]
                    + aE * d[2][j][c];
#pragma unroll
            for (int dl = 4; dl <= 16; dl <<= 1)
                v += __shfl_xor_sync(0xffffffffu, v, dl);
            pm[j][c] = v;
        }

    // ---- target row 0 (held by g==0 lanes) ----
    float tv[4][2];
    float tsm = 0.f, ts2 = 0.f;
#pragma unroll
    for (int j = 0; j < 4; ++j)
#pragma unroll
        for (int c = 0; c < 2; ++c) {
            float v = d[0][j][c] + pm[j][c];
            tv[j][c] = v;
            tsm += v;
            ts2 = fmaf(v, v, ts2);
        }
#pragma unroll
    for (int dl = 1; dl <= 2; dl <<= 1) {
        tsm += __shfl_xor_sync(0xffffffffu, tsm, dl);
        ts2 += __shfl_xor_sync(0xffffffffu, ts2, dl);
    }
    if (lane == 0) sT[bl][half] = make_float2(tsm, ts2);
    BARX(barid);

    if (lane < 4) {  // g==0, t=0..3 lanes write target row
        float2 v0 = sT[bl][0], v1 = sT[bl][1];
        float mu  = (v0.x + v1.x) * (1.f / 64.f);
        float var = fmaf(v0.y + v1.y, 1.f / 64.f, -mu * mu);
        float ri  = rsqrtf(var + EPSLN);
#pragma unroll
        for (int j = 0; j < 4; ++j) {
            float2 o;
            o.x = fmaf((tv[j][0] - mu) * ri, g2[j].x, be2[j].x);
            o.y = fmaf((tv[j][1] - mu) * ri, g2[j].y, be2[j].y);
            *(float2*)(gO + col0 + j * 8) = o;
        }
    }
}

extern "C" void kernel_launch(void* const* d_in, const int* in_sizes, int n_in,
                              void* d_out, int out_size) {
    const float* nodes = (const float*)d_in[0];
    const float* edges = (const float*)d_in[1];
    const float* Ww    = (const float*)d_in[2];
    const float* Wb    = (const float*)d_in[3];
    const float* Wew   = (const float*)d_in[4];
    // d_in[5] = We_b   (cancels under softmax shift-invariance)
    const float* attw  = (const float*)d_in[6];
    // d_in[7] = attn_b (cancels under softmax shift-invariance)
    const float* gamma = (const float*)d_in[8];
    const float* beta  = (const float*)d_in[9];

    gat_kernel<<<16384 / 4, 256>>>(nodes, edges, Ww, Wb, Wew, attw, gamma, beta,
                                   (float*)d_out);
}

// round 13
// speedup vs baseline: 1.0790x; 1.0790x over previous
#include <cuda_runtime.h>

#define EPSLN 1e-5f
#define RS 68   // smem row stride in floats (4g+t bank pattern -> conflict-free)

// Precomputed per launch (deterministic, graph-capturable)
// B fragment for m16n8k8.row.col: b0 = W[ks*8+t][nt*8+g], b1 = W[ks*8+t+4][nt*8+g]
__device__ __align__(16) uint2 g_Wfrag[8 * 8 * 32];
__device__ __align__(16) float g_ewproj[16];         // We_w @ attn_w[128:192]

__device__ __forceinline__ unsigned cvt_tf32(float x) {
    unsigned r; asm("cvt.rna.tf32.f32 %0, %1;" : "=r"(r) : "f"(x)); return r;
}

#define MMA_TF32(d, a, b)                                                          \
    asm volatile(                                                                  \
        "mma.sync.aligned.m16n8k8.row.col.f32.tf32.tf32.f32 "                      \
        "{%0,%1,%2,%3},{%4,%5,%6,%7},{%8,%9},{%0,%1,%2,%3};"                       \
        : "+f"(d[0]), "+f"(d[1]), "+f"(d[2]), "+f"(d[3])                           \
        : "r"(a[0]), "r"(a[1]), "r"(a[2]), "r"(a[3]), "r"(b[0]), "r"(b[1]))

// Named barrier over the 64 threads (2 warps) serving one batch
#define BARX(id) asm volatile("bar.sync %0, 64;" :: "r"(id) : "memory")

#define CP_ASYNC16(dst_u32, src_ptr)                                               \
    asm volatile("cp.async.cg.shared.global [%0], [%1], 16;"                       \
                 :: "r"(dst_u32), "l"(src_ptr))

__global__ void prep_kernel(const float* __restrict__ Ww,
                            const float* __restrict__ Wew,
                            const float* __restrict__ attw) {
    int tid = threadIdx.x;  // 128 threads, 16 blocks
    if (blockIdx.x == 0 && tid < 16) {
        float se = 0.f;
#pragma unroll 8
        for (int o = 0; o < 64; ++o) se += Wew[tid * 64 + o] * attw[128 + o];
        g_ewproj[tid] = se;
    }
    int idx = blockIdx.x * 128 + tid;   // 16*128 = 2048 exactly
    {
        int lane = idx & 31;
        int nt   = (idx >> 5) & 7;
        int ks   = idx >> 8;
        int t = lane & 3, g = lane >> 2;
        uint2 v;
        v.x = cvt_tf32(Ww[(ks * 8 + t) * 64 + nt * 8 + g]);
        v.y = cvt_tf32(Ww[(ks * 8 + t + 4) * 64 + nt * 8 + g]);
        g_Wfrag[idx] = v;
    }
}

__global__ __launch_bounds__(256, 3) void gat_kernel(
    const float* __restrict__ nodes,
    const float* __restrict__ edges,
    const float* __restrict__ Wbias,
    const float* __restrict__ attw,
    const float* __restrict__ gamma,
    const float* __restrict__ beta,
    float* __restrict__ out)
{
    __shared__ float  sN[4][33 * RS];        // nodes, raw fp32 (MMA truncates to tf32)
    __shared__ uint2  sB[8 * 8 * 32];        // weight fragments (16 KB)
    __shared__ float2 sSum[4][2][33];        // (sum, sumsq) per row/half
    __shared__ float  sScore[4][2][32];      // attention scores rows 1..32
    __shared__ float  sAttn[4][32];
    __shared__ float2 sT[4][2];              // target LN partials per half

    const int tid  = threadIdx.x;
    const int lane = tid & 31;
    const int warp = tid >> 5;
    const int bl   = warp >> 1;     // batch within CTA (0..3)
    const int half = warp & 1;      // column half (32 cols)
    const int t    = lane & 3;      // threadID-in-group
    const int g    = lane >> 2;     // groupID
    const long long b = (long long)blockIdx.x * 4 + bl;
    const int barid = bl + 1;

    // ---- stage nodes via cp.async (no RF round-trip, no STS wavefronts) ----
    const float4* srcAll = (const float4*)(nodes + (long long)blockIdx.x * 4 * 2112);
#pragma unroll
    for (int qq = 0; qq < 9; ++qq) {
        int q = tid + qq * 256;
        if (q < 2112) {
            int bb = q / 528;
            int ql = q - bb * 528;
            int r  = ql >> 4, i4 = ql & 15;
            unsigned dst = (unsigned)__cvta_generic_to_shared(&sN[bb][r * RS + i4 * 4]);
            CP_ASYNC16(dst, srcAll + q);
        }
    }
    asm volatile("cp.async.commit_group;" ::: "memory");

    // ---- stage weights (16 KB, once per CTA / 4 batches) ----
    for (int q = tid; q < 2048; q += 256) sB[q] = g_Wfrag[q];

    // ---- edge score term (half==0 warps, lane = neighbor k) ----
    float ek = 0.f;
    if (half == 0) {
        const float4* er = (const float4*)(edges + (b * 32 + lane) * 16);
#pragma unroll
        for (int e4 = 0; e4 < 4; ++e4) {
            float4 a = er[e4];
            float4 w = *(const float4*)&g_ewproj[e4 * 4];
            ek += a.x * w.x + a.y * w.y + a.z * w.z + a.w * w.w;
        }
    }

    asm volatile("cp.async.wait_group 0;" ::: "memory");
    __syncthreads();  // staging complete (CTA-wide, once)

    // ---- tensor-core GEMM: 3 m16 tiles x 4 n8 tiles (this warp's half) ----
    // A operands fed as raw fp32 bits (HW reads top 19 bits = tf32 truncation).
    const unsigned* sNb = (const unsigned*)sN[bl];
    float d[3][4][4];
#pragma unroll
    for (int m = 0; m < 3; ++m)
#pragma unroll
        for (int j = 0; j < 4; ++j)
#pragma unroll
            for (int c = 0; c < 4; ++c) d[m][j][c] = 0.f;

#pragma unroll
    for (int ks = 0; ks < 8; ++ks) {
        unsigned bb[4][2];
#pragma unroll
        for (int j = 0; j < 4; ++j) {
            uint2 v = sB[(ks * 8 + half * 4 + j) * 32 + lane];
            bb[j][0] = v.x; bb[j][1] = v.y;
        }
        unsigned aa[3][4];
#pragma unroll
        for (int m = 0; m < 2; ++m) {
            int base = (m * 16 + g) * RS + ks * 8 + t;
            aa[m][0] = sNb[base];
            aa[m][1] = sNb[base + 8 * RS];
            aa[m][2] = sNb[base + 4];
            aa[m][3] = sNb[base + 8 * RS + 4];
        }
        if (g == 0) {   // m-tile 2: only row 32 real
            int base = 32 * RS + ks * 8 + t;
            aa[2][0] = sNb[base];
            aa[2][2] = sNb[base + 4];
        } else { aa[2][0] = 0u; aa[2][2] = 0u; }
        aa[2][1] = 0u; aa[2][3] = 0u;

#pragma unroll
        for (int m = 0; m < 3; ++m)
#pragma unroll
            for (int j = 0; j < 4; ++j)
                MMA_TF32(d[m][j], aa[m], bb[j]);
    }

    // ---- epilogue params (post-GEMM to keep mainloop registers lean) ----
    const int col0 = half * 32 + 2 * t;
    float2 wb2[4], aw2[4], g2[4], be2[4];
#pragma unroll
    for (int j = 0; j < 4; ++j) {
        wb2[j] = *(const float2*)(Wbias + col0 + j * 8);
        aw2[j] = *(const float2*)(attw + 64 + col0 + j * 8);
        g2[j]  = *(const float2*)(gamma + col0 + j * 8);
        be2[j] = *(const float2*)(beta  + col0 + j * 8);
    }

    // ---- add bias; per-row stats (sum, sumsq, score) ----
#pragma unroll
    for (int m = 0; m < 3; ++m)
#pragma unroll
        for (int j = 0; j < 4; ++j) {
            d[m][j][0] += wb2[j].x; d[m][j][1] += wb2[j].y;
            d[m][j][2] += wb2[j].x; d[m][j][3] += wb2[j].y;
        }

    float sm[3][2], s2[3][2], sc[3][2];
#pragma unroll
    for (int m = 0; m < 3; ++m)
#pragma unroll
        for (int rh = 0; rh < 2; ++rh) {
            float a = 0.f, q = 0.f, s = 0.f;
#pragma unroll
            for (int j = 0; j < 4; ++j) {
                float h0 = d[m][j][rh * 2], h1 = d[m][j][rh * 2 + 1];
                a += h0 + h1;
                q = fmaf(h0, h0, fmaf(h1, h1, q));
                s = fmaf(h0, aw2[j].x, fmaf(h1, aw2[j].y, s));
            }
#pragma unroll
            for (int dl = 1; dl <= 2; dl <<= 1) {
                a += __shfl_xor_sync(0xffffffffu, a, dl);
                q += __shfl_xor_sync(0xffffffffu, q, dl);
                s += __shfl_xor_sync(0xffffffffu, s, dl);
            }
            sm[m][rh] = a; s2[m][rh] = q; sc[m][rh] = s;
        }
    if (t == 0) {
        sSum[bl][half][g]      = make_float2(sm[0][0], s2[0][0]);
        sSum[bl][half][g + 8]  = make_float2(sm[0][1], s2[0][1]);
        sSum[bl][half][g + 16] = make_float2(sm[1][0], s2[1][0]);
        sSum[bl][half][g + 24] = make_float2(sm[1][1], s2[1][1]);
        if (g > 0) sScore[bl][half][g - 1] = sc[0][0];
        sScore[bl][half][g + 7]  = sc[0][1];   // row g+8
        sScore[bl][half][g + 15] = sc[1][0];   // row 16+g
        sScore[bl][half][g + 23] = sc[1][1];   // row 24+g
        if (g == 0) {
            sSum[bl][half][32]   = make_float2(sm[2][0], s2[2][0]);
            sScore[bl][half][31] = sc[2][0];   // row 32
        }
    }
    BARX(barid);   // only this batch's 2 warps

    // ---- layernorm + store for neighbor rows (1..32) ----
    float* gO = out + b * 2112;
#pragma unroll
    for (int m = 0; m < 3; ++m)
#pragma unroll
        for (int rh = 0; rh < 2; ++rh) {
            int row = m * 16 + g + rh * 8;
            bool valid = (row >= 1) && (row <= 32) && !(m == 2 && !(g == 0 && rh == 0));
            if (valid) {
                float2 u0 = sSum[bl][0][row];
                float2 u1 = sSum[bl][1][row];
                float mu  = (u0.x + u1.x) * (1.f / 64.f);
                float var = fmaf(u0.y + u1.y, 1.f / 64.f, -mu * mu);
                float ri  = rsqrtf(var + EPSLN);
#pragma unroll
                for (int j = 0; j < 4; ++j) {
                    float2 o;
                    o.x = fmaf((d[m][j][rh * 2]     - mu) * ri, g2[j].x, be2[j].x);
                    o.y = fmaf((d[m][j][rh * 2 + 1] - mu) * ri, g2[j].y, be2[j].y);
                    *(float2*)(gO + row * 64 + col0 + j * 8) = o;
                }
            }
        }

    // ---- softmax over 32 neighbor scores (half==0 warp of each batch) ----
    if (half == 0) {
        float s = sScore[bl][0][lane] + sScore[bl][1][lane] + ek;
        float mx = s;
#pragma unroll
        for (int dl = 16; dl > 0; dl >>= 1) mx = fmaxf(mx, __shfl_xor_sync(0xffffffffu, mx, dl));
        float p = __expf(s - mx);
        float tot = p;
#pragma unroll
        for (int dl = 16; dl > 0; dl >>= 1) tot += __shfl_xor_sync(0xffffffffu, tot, dl);
        sAttn[bl][lane] = p / tot;
    }
    BARX(barid);

    // ---- messages: msg[col] = sum_k attn_k * h_k[col] ----
    float aA = (g > 0) ? sAttn[bl][g - 1] : 0.f;   // row g
    float aB = sAttn[bl][g + 7];                    // row g+8
    float aC = sAttn[bl][g + 15];                   // row 16+g
    float aD = sAttn[bl][g + 23];                   // row 24+g
    float aE = (g == 0) ? sAttn[bl][31] : 0.f;      // row 32

    float pm[4][2];
#pragma unroll
    for (int j = 0; j < 4; ++j)
#pragma unroll
        for (int c = 0; c < 2; ++c) {
            float v = aA * d[0][j][c] + aB * d[0][j][2 + c]
                    + aC * d[1][j][c] + aD * d[1][j][2 + c]
                    + aE * d[2][j][c];
#pragma unroll
            for (int dl = 4; dl <= 16; dl <<= 1)
                v += __shfl_xor_sync(0xffffffffu, v, dl);
            pm[j][c] = v;
        }

    // ---- target row 0 (held by g==0 lanes) ----
    float tv[4][2];
    float tsm = 0.f, ts2 = 0.f;
#pragma unroll
    for (int j = 0; j < 4; ++j)
#pragma unroll
        for (int c = 0; c < 2; ++c) {
            float v = d[0][j][c] + pm[j][c];
            tv[j][c] = v;
            tsm += v;
            ts2 = fmaf(v, v, ts2);
        }
#pragma unroll
    for (int dl = 1; dl <= 2; dl <<= 1) {
        tsm += __shfl_xor_sync(0xffffffffu, tsm, dl);
        ts2 += __shfl_xor_sync(0xffffffffu, ts2, dl);
    }
    if (lane == 0) sT[bl][half] = make_float2(tsm, ts2);
    BARX(barid);

    if (lane < 4) {  // g==0, t=0..3 lanes write target row
        float2 v0 = sT[bl][0], v1 = sT[bl][1];
        float mu  = (v0.x + v1.x) * (1.f / 64.f);
        float var = fmaf(v0.y + v1.y, 1.f / 64.f, -mu * mu);
        float ri  = rsqrtf(var + EPSLN);
#pragma unroll
        for (int j = 0; j < 4; ++j) {
            float2 o;
            o.x = fmaf((tv[j][0] - mu) * ri, g2[j].x, be2[j].x);
            o.y = fmaf((tv[j][1] - mu) * ri, g2[j].y, be2[j].y);
            *(float2*)(gO + col0 + j * 8) = o;
        }
    }
}

extern "C" void kernel_launch(void* const* d_in, const int* in_sizes, int n_in,
                              void* d_out, int out_size) {
    const float* nodes = (const float*)d_in[0];
    const float* edges = (const float*)d_in[1];
    const float* Ww    = (const float*)d_in[2];
    const float* Wb    = (const float*)d_in[3];
    const float* Wew   = (const float*)d_in[4];
    // d_in[5] = We_b   (cancels under softmax shift-invariance)
    const float* attw  = (const float*)d_in[6];
    // d_in[7] = attn_b (cancels under softmax shift-invariance)
    const float* gamma = (const float*)d_in[8];
    const float* beta  = (const float*)d_in[9];

    prep_kernel<<<16, 128>>>(Ww, Wew, attw);
    gat_kernel<<<16384 / 4, 256>>>(nodes, edges, Wb, attw, gamma, beta, (float*)d_out);
}

// round 14
// speedup vs baseline: 1.0996x; 1.0191x over previous
#include <cuda_runtime.h>

#define EPSLN 1e-5f
#define RS 68   // smem row stride in floats (4g+t bank pattern -> conflict-free)

// Precomputed per launch (deterministic, graph-capturable)
// B fragment for m16n8k8.row.col: b0 = W[ks*8+t][nt*8+g], b1 = W[ks*8+t+4][nt*8+g]
__device__ __align__(16) uint2 g_Wfrag[8 * 8 * 32];
__device__ __align__(16) float g_ewproj[16];         // We_w @ attn_w[128:192]

__device__ __forceinline__ unsigned cvt_tf32(float x) {
    unsigned r; asm("cvt.rna.tf32.f32 %0, %1;" : "=r"(r) : "f"(x)); return r;
}

#define MMA_TF32(d, a, b)                                                          \
    asm volatile(                                                                  \
        "mma.sync.aligned.m16n8k8.row.col.f32.tf32.tf32.f32 "                      \
        "{%0,%1,%2,%3},{%4,%5,%6,%7},{%8,%9},{%0,%1,%2,%3};"                       \
        : "+f"(d[0]), "+f"(d[1]), "+f"(d[2]), "+f"(d[3])                           \
        : "r"(a[0]), "r"(a[1]), "r"(a[2]), "r"(a[3]), "r"(b[0]), "r"(b[1]))

// Named barrier over the 64 threads (2 warps) serving one batch
#define BARX(id) asm volatile("bar.sync %0, 64;" :: "r"(id) : "memory")

#define CP_ASYNC16(dst_u32, src_ptr)                                               \
    asm volatile("cp.async.cg.shared.global [%0], [%1], 16;"                       \
                 :: "r"(dst_u32), "l"(src_ptr))

__global__ void prep_kernel(const float* __restrict__ Ww,
                            const float* __restrict__ Wew,
                            const float* __restrict__ attw) {
    int tid = threadIdx.x;  // 128 threads, 16 blocks
    if (blockIdx.x == 0) {
        // ewproj[e] = sum_o Wew[e][o] * attw[64+64+o]; 8 threads per e
        int e = tid >> 3, sub = tid & 7;
        float p = 0.f;
#pragma unroll
        for (int o = 0; o < 8; ++o)
            p += Wew[e * 64 + sub * 8 + o] * attw[128 + sub * 8 + o];
#pragma unroll
        for (int dl = 1; dl <= 4; dl <<= 1)
            p += __shfl_xor_sync(0xffffffffu, p, dl);
        if (sub == 0) g_ewproj[e] = p;
    }
    int idx = blockIdx.x * 128 + tid;   // 16*128 = 2048 exactly
    {
        int lane = idx & 31;
        int nt   = (idx >> 5) & 7;
        int ks   = idx >> 8;
        int t = lane & 3, g = lane >> 2;
        uint2 v;
        v.x = cvt_tf32(Ww[(ks * 8 + t) * 64 + nt * 8 + g]);
        v.y = cvt_tf32(Ww[(ks * 8 + t + 4) * 64 + nt * 8 + g]);
        g_Wfrag[idx] = v;
    }
}

__global__ __launch_bounds__(256, 3) void gat_kernel(
    const float* __restrict__ nodes,
    const float* __restrict__ edges,
    const float* __restrict__ Wbias,
    const float* __restrict__ attw,
    const float* __restrict__ gamma,
    const float* __restrict__ beta,
    float* __restrict__ out)
{
    __shared__ float  sN[4][33 * RS];        // nodes, raw fp32 (MMA truncates to tf32)
    __shared__ uint2  sB[8 * 8 * 32];        // weight fragments (16 KB)
    __shared__ float2 sSum[4][2][33];        // (sum, sumsq) per row/half
    __shared__ float  sScore[4][2][32];      // partial attention scores rows 1..32
    __shared__ float  sEk[4][32];            // edge score terms per neighbor
    __shared__ float2 sT[4][2];              // target LN partials per half

    const int tid  = threadIdx.x;
    const int lane = tid & 31;
    const int warp = tid >> 5;
    const int bl   = warp >> 1;     // batch within CTA (0..3)
    const int half = warp & 1;      // column half (32 cols)
    const int t    = lane & 3;      // threadID-in-group
    const int g    = lane >> 2;     // groupID
    const long long b = (long long)blockIdx.x * 4 + bl;
    const int barid = bl + 1;

    // ---- stage nodes via cp.async (no RF round-trip, no STS wavefronts) ----
    const float4* srcAll = (const float4*)(nodes + (long long)blockIdx.x * 4 * 2112);
#pragma unroll
    for (int qq = 0; qq < 9; ++qq) {
        int q = tid + qq * 256;
        if (q < 2112) {
            int bb = q / 528;
            int ql = q - bb * 528;
            int r  = ql >> 4, i4 = ql & 15;
            unsigned dst = (unsigned)__cvta_generic_to_shared(&sN[bb][r * RS + i4 * 4]);
            CP_ASYNC16(dst, srcAll + q);
        }
    }
    asm volatile("cp.async.commit_group;" ::: "memory");

    // ---- stage weights (16 KB, once per CTA / 4 batches) ----
    for (int q = tid; q < 2048; q += 256) sB[q] = g_Wfrag[q];

    // ---- edge score term (half==0 warps, lane = neighbor k) ----
    if (half == 0) {
        const float4* er = (const float4*)(edges + (b * 32 + lane) * 16);
        float ek = 0.f;
#pragma unroll
        for (int e4 = 0; e4 < 4; ++e4) {
            float4 a = er[e4];
            float4 w = *(const float4*)&g_ewproj[e4 * 4];
            ek += a.x * w.x + a.y * w.y + a.z * w.z + a.w * w.w;
        }
        sEk[bl][lane] = ek;
    }

    asm volatile("cp.async.wait_group 0;" ::: "memory");
    __syncthreads();  // staging complete (CTA-wide, once)

    // ---- tensor-core GEMM: 3 m16 tiles x 4 n8 tiles (this warp's half) ----
    // A operands fed as raw fp32 bits (HW reads top 19 bits = tf32 truncation).
    const unsigned* sNb = (const unsigned*)sN[bl];
    float d[3][4][4];
#pragma unroll
    for (int m = 0; m < 3; ++m)
#pragma unroll
        for (int j = 0; j < 4; ++j)
#pragma unroll
            for (int c = 0; c < 4; ++c) d[m][j][c] = 0.f;

#pragma unroll
    for (int ks = 0; ks < 8; ++ks) {
        unsigned bb[4][2];
#pragma unroll
        for (int j = 0; j < 4; ++j) {
            uint2 v = sB[(ks * 8 + half * 4 + j) * 32 + lane];
            bb[j][0] = v.x; bb[j][1] = v.y;
        }
        unsigned aa[3][4];
#pragma unroll
        for (int m = 0; m < 2; ++m) {
            int base = (m * 16 + g) * RS + ks * 8 + t;
            aa[m][0] = sNb[base];
            aa[m][1] = sNb[base + 8 * RS];
            aa[m][2] = sNb[base + 4];
            aa[m][3] = sNb[base + 8 * RS + 4];
        }
        if (g == 0) {   // m-tile 2: only row 32 real
            int base = 32 * RS + ks * 8 + t;
            aa[2][0] = sNb[base];
            aa[2][2] = sNb[base + 4];
        } else { aa[2][0] = 0u; aa[2][2] = 0u; }
        aa[2][1] = 0u; aa[2][3] = 0u;

#pragma unroll
        for (int m = 0; m < 3; ++m)
#pragma unroll
            for (int j = 0; j < 4; ++j)
                MMA_TF32(d[m][j], aa[m], bb[j]);
    }

    // ---- epilogue params (post-GEMM to keep mainloop registers lean) ----
    const int col0 = half * 32 + 2 * t;
    float2 wb2[4], aw2[4], g2[4], be2[4];
#pragma unroll
    for (int j = 0; j < 4; ++j) {
        wb2[j] = *(const float2*)(Wbias + col0 + j * 8);
        aw2[j] = *(const float2*)(attw + 64 + col0 + j * 8);
        g2[j]  = *(const float2*)(gamma + col0 + j * 8);
        be2[j] = *(const float2*)(beta  + col0 + j * 8);
    }

    // ---- add bias; per-row stats (sum, sumsq, score) ----
#pragma unroll
    for (int m = 0; m < 3; ++m)
#pragma unroll
        for (int j = 0; j < 4; ++j) {
            d[m][j][0] += wb2[j].x; d[m][j][1] += wb2[j].y;
            d[m][j][2] += wb2[j].x; d[m][j][3] += wb2[j].y;
        }

    float sm[3][2], s2[3][2], sc[3][2];
#pragma unroll
    for (int m = 0; m < 3; ++m)
#pragma unroll
        for (int rh = 0; rh < 2; ++rh) {
            float a = 0.f, q = 0.f, s = 0.f;
#pragma unroll
            for (int j = 0; j < 4; ++j) {
                float h0 = d[m][j][rh * 2], h1 = d[m][j][rh * 2 + 1];
                a += h0 + h1;
                q = fmaf(h0, h0, fmaf(h1, h1, q));
                s = fmaf(h0, aw2[j].x, fmaf(h1, aw2[j].y, s));
            }
#pragma unroll
            for (int dl = 1; dl <= 2; dl <<= 1) {
                a += __shfl_xor_sync(0xffffffffu, a, dl);
                q += __shfl_xor_sync(0xffffffffu, q, dl);
                s += __shfl_xor_sync(0xffffffffu, s, dl);
            }
            sm[m][rh] = a; s2[m][rh] = q; sc[m][rh] = s;
        }
    if (t == 0) {
        sSum[bl][half][g]      = make_float2(sm[0][0], s2[0][0]);
        sSum[bl][half][g + 8]  = make_float2(sm[0][1], s2[0][1]);
        sSum[bl][half][g + 16] = make_float2(sm[1][0], s2[1][0]);
        sSum[bl][half][g + 24] = make_float2(sm[1][1], s2[1][1]);
        if (g > 0) sScore[bl][half][g - 1] = sc[0][0];
        sScore[bl][half][g + 7]  = sc[0][1];   // row g+8
        sScore[bl][half][g + 15] = sc[1][0];   // row 16+g
        sScore[bl][half][g + 23] = sc[1][1];   // row 24+g
        if (g == 0) {
            sSum[bl][half][32]   = make_float2(sm[2][0], s2[2][0]);
            sScore[bl][half][31] = sc[2][0];   // row 32
        }
    }
    BARX(barid);   // only this batch's 2 warps (sSum/sScore/sEk visible)

    // ---- softmax (both warps redundantly, registers; scores are tiny so
    //      the max-shift is unnecessary: |s| << 80) ----
    float p = __expf(sScore[bl][0][lane] + sScore[bl][1][lane] + sEk[bl][lane]);
    float tot = p;
#pragma unroll
    for (int dl = 16; dl > 0; dl >>= 1) tot += __shfl_xor_sync(0xffffffffu, tot, dl);
    const float attn = p / tot;   // lane k holds attn for neighbor row k+1

    // ---- layernorm + store for neighbor rows (1..32) ----
    float* gO = out + b * 2112;
#pragma unroll
    for (int m = 0; m < 3; ++m)
#pragma unroll
        for (int rh = 0; rh < 2; ++rh) {
            int row = m * 16 + g + rh * 8;
            bool valid = (row >= 1) && (row <= 32) && !(m == 2 && !(g == 0 && rh == 0));
            if (valid) {
                float2 u0 = sSum[bl][0][row];
                float2 u1 = sSum[bl][1][row];
                float mu  = (u0.x + u1.x) * (1.f / 64.f);
                float var = fmaf(u0.y + u1.y, 1.f / 64.f, -mu * mu);
                float ri  = rsqrtf(var + EPSLN);
#pragma unroll
                for (int j = 0; j < 4; ++j) {
                    float2 o;
                    o.x = fmaf((d[m][j][rh * 2]     - mu) * ri, g2[j].x, be2[j].x);
                    o.y = fmaf((d[m][j][rh * 2 + 1] - mu) * ri, g2[j].y, be2[j].y);
                    *(float2*)(gO + row * 64 + col0 + j * 8) = o;
                }
            }
        }

    // ---- message coefficients via in-register shuffles (no barrier) ----
    float aA = __shfl_sync(0xffffffffu, attn, (g == 0) ? 0 : (g - 1));
    if (g == 0) aA = 0.f;                                  // row g   (g>=1)
    float aB = __shfl_sync(0xffffffffu, attn, g + 7);      // row g+8
    float aC = __shfl_sync(0xffffffffu, attn, g + 15);     // row 16+g
    float aD = __shfl_sync(0xffffffffu, attn, g + 23);     // row 24+g
    float aE = __shfl_sync(0xffffffffu, attn, 31);         // row 32
    if (g != 0) aE = 0.f;

    float pm[4][2];
#pragma unroll
    for (int j = 0; j < 4; ++j)
#pragma unroll
        for (int c = 0; c < 2; ++c) {
            float v = aA * d[0][j][c] + aB * d[0][j][2 + c]
                    + aC * d[1][j][c] + aD * d[1][j][2 + c]
                    + aE * d[2][j][c];
#pragma unroll
            for (int dl = 4; dl <= 16; dl <<= 1)
                v += __shfl_xor_sync(0xffffffffu, v, dl);
            pm[j][c] = v;
        }

    // ---- target row 0 (held by g==0 lanes) ----
    float tv[4][2];
    float tsm = 0.f, ts2 = 0.f;
#pragma unroll
    for (int j = 0; j < 4; ++j)
#pragma unroll
        for (int c = 0; c < 2; ++c) {
            float v = d[0][j][c] + pm[j][c];
            tv[j][c] = v;
            tsm += v;
            ts2 = fmaf(v, v, ts2);
        }
#pragma unroll
    for (int dl = 1; dl <= 2; dl <<= 1) {
        tsm += __shfl_xor_sync(0xffffffffu, tsm, dl);
        ts2 += __shfl_xor_sync(0xffffffffu, ts2, dl);
    }
    if (lane == 0) sT[bl][half] = make_float2(tsm, ts2);
    BARX(barid);

    if (lane < 4) {  // g==0, t=0..3 lanes write target row
        float2 v0 = sT[bl][0], v1 = sT[bl][1];
        float mu  = (v0.x + v1.x) * (1.f / 64.f);
        float var = fmaf(v0.y + v1.y, 1.f / 64.f, -mu * mu);
        float ri  = rsqrtf(var + EPSLN);
#pragma unroll
        for (int j = 0; j < 4; ++j) {
            float2 o;
            o.x = fmaf((tv[j][0] - mu) * ri, g2[j].x, be2[j].x);
            o.y = fmaf((tv[j][1] - mu) * ri, g2[j].y, be2[j].y);
            *(float2*)(gO + col0 + j * 8) = o;
        }
    }
}

extern "C" void kernel_launch(void* const* d_in, const int* in_sizes, int n_in,
                              void* d_out, int out_size) {
    const float* nodes = (const float*)d_in[0];
    const float* edges = (const float*)d_in[1];
    const float* Ww    = (const float*)d_in[2];
    const float* Wb    = (const float*)d_in[3];
    const float* Wew   = (const float*)d_in[4];
    // d_in[5] = We_b   (cancels under softmax shift-invariance)
    const float* attw  = (const float*)d_in[6];
    // d_in[7] = attn_b (cancels under softmax shift-invariance)
    const float* gamma = (const float*)d_in[8];
    const float* beta  = (const float*)d_in[9];

    prep_kernel<<<16, 128>>>(Ww, Wew, attw);
    gat_kernel<<<16384 / 4, 256>>>(nodes, edges, Wb, attw, gamma, beta, (float*)d_out);
}

// round 15
// speedup vs baseline: 1.1402x; 1.0369x over previous
#include <cuda_runtime.h>

#define EPSLN 1e-5f
#define RS 68   // smem row stride in floats (4g+t bank pattern -> conflict-free)

// Precomputed per launch (deterministic, graph-capturable)
// B fragment for m16n8k8.row.col: b0 = W[ks*8+t][nt*8+g], b1 = W[ks*8+t+4][nt*8+g]
__device__ __align__(16) uint2 g_Wfrag[8 * 8 * 32];
__device__ __align__(16) float g_ewproj[16];         // We_w @ attn_w[128:192]

__device__ __forceinline__ unsigned cvt_tf32(float x) {
    unsigned r; asm("cvt.rna.tf32.f32 %0, %1;" : "=r"(r) : "f"(x)); return r;
}

#define MMA_TF32(d, a, b)                                                          \
    asm volatile(                                                                  \
        "mma.sync.aligned.m16n8k8.row.col.f32.tf32.tf32.f32 "                      \
        "{%0,%1,%2,%3},{%4,%5,%6,%7},{%8,%9},{%0,%1,%2,%3};"                       \
        : "+f"(d[0]), "+f"(d[1]), "+f"(d[2]), "+f"(d[3])                           \
        : "r"(a[0]), "r"(a[1]), "r"(a[2]), "r"(a[3]), "r"(b[0]), "r"(b[1]))

// Named barrier over the 64 threads (2 warps) serving one batch
#define BARX(id) asm volatile("bar.sync %0, 64;" :: "r"(id) : "memory")

#define CP_ASYNC16(dst_u32, src_ptr)                                               \
    asm volatile("cp.async.cg.shared.global [%0], [%1], 16;"                       \
                 :: "r"(dst_u32), "l"(src_ptr))

__global__ void prep_kernel(const float* __restrict__ Ww,
                            const float* __restrict__ Wew,
                            const float* __restrict__ attw) {
    int tid = threadIdx.x;  // 128 threads, 16 blocks
    if (blockIdx.x == 0) {
        // ewproj[e] = sum_o Wew[e][o] * attw[128+o]; 8 threads per e
        int e = tid >> 3, sub = tid & 7;
        float p = 0.f;
#pragma unroll
        for (int o = 0; o < 8; ++o)
            p += Wew[e * 64 + sub * 8 + o] * attw[128 + sub * 8 + o];
#pragma unroll
        for (int dl = 1; dl <= 4; dl <<= 1)
            p += __shfl_xor_sync(0xffffffffu, p, dl);
        if (sub == 0) g_ewproj[e] = p;
    }
    int idx = blockIdx.x * 128 + tid;   // 16*128 = 2048 exactly
    {
        int lane = idx & 31;
        int nt   = (idx >> 5) & 7;
        int ks   = idx >> 8;
        int t = lane & 3, g = lane >> 2;
        uint2 v;
        v.x = cvt_tf32(Ww[(ks * 8 + t) * 64 + nt * 8 + g]);
        v.y = cvt_tf32(Ww[(ks * 8 + t + 4) * 64 + nt * 8 + g]);
        g_Wfrag[idx] = v;
    }
}

__global__ __launch_bounds__(256, 3) void gat_kernel(
    const float* __restrict__ nodes,
    const float* __restrict__ edges,
    const float* __restrict__ Wbias,
    const float* __restrict__ attw,
    const float* __restrict__ gamma,
    const float* __restrict__ beta,
    float* __restrict__ out)
{
    __shared__ float  sN[4][33 * RS];        // nodes, raw fp32 (MMA truncates to tf32)
    __shared__ uint2  sB[8 * 8 * 32];        // weight fragments (16 KB)
    __shared__ float2 sSum[4][2][33];        // (sum, sumsq) per row/half
    __shared__ float  sScore[4][2][32];      // partial attention scores rows 1..32
    __shared__ float  sEk[4][32];            // edge score terms per neighbor
    __shared__ float2 sT[4][2];              // target LN partials per half

    const int tid  = threadIdx.x;
    const int lane = tid & 31;
    const int warp = tid >> 5;
    const int bl   = warp >> 1;     // batch within CTA (0..3)
    const int half = warp & 1;      // column half (32 cols)
    const int t    = lane & 3;      // threadID-in-group
    const int g    = lane >> 2;     // groupID
    const long long b = (long long)blockIdx.x * 4 + bl;
    const int barid = bl + 1;

    // ---- stage nodes via cp.async (independent of prep -> issue BEFORE the
    //      grid dependency sync so prep overlaps this DRAM latency) ----
    const float4* srcAll = (const float4*)(nodes + (long long)blockIdx.x * 4 * 2112);
#pragma unroll
    for (int qq = 0; qq < 9; ++qq) {
        int q = tid + qq * 256;
        if (q < 2112) {
            int bb = q / 528;
            int ql = q - bb * 528;
            int r  = ql >> 4, i4 = ql & 15;
            unsigned dst = (unsigned)__cvta_generic_to_shared(&sN[bb][r * RS + i4 * 4]);
            CP_ASYNC16(dst, srcAll + q);
        }
    }
    asm volatile("cp.async.commit_group;" ::: "memory");

    // ---- PDL: wait for prep_kernel's g_Wfrag / g_ewproj before reading ----
    cudaGridDependencySynchronize();

    // ---- stage weights (16 KB, once per CTA / 4 batches) ----
    for (int q = tid; q < 2048; q += 256) sB[q] = g_Wfrag[q];

    // ---- edge score term (half==0 warps, lane = neighbor k) ----
    if (half == 0) {
        const float4* er = (const float4*)(edges + (b * 32 + lane) * 16);
        float ek = 0.f;
#pragma unroll
        for (int e4 = 0; e4 < 4; ++e4) {
            float4 a = er[e4];
            float4 w = *(const float4*)&g_ewproj[e4 * 4];
            ek += a.x * w.x + a.y * w.y + a.z * w.z + a.w * w.w;
        }
        sEk[bl][lane] = ek;
    }

    asm volatile("cp.async.wait_group 0;" ::: "memory");
    __syncthreads();  // staging complete (CTA-wide, once)

    // ---- tensor-core GEMM: 3 m16 tiles x 4 n8 tiles (this warp's half) ----
    // A operands fed as raw fp32 bits (HW reads top 19 bits = tf32 truncation).
    const unsigned* sNb = (const unsigned*)sN[bl];
    float d[3][4][4];
#pragma unroll
    for (int m = 0; m < 3; ++m)
#pragma unroll
        for (int j = 0; j < 4; ++j)
#pragma unroll
            for (int c = 0; c < 4; ++c) d[m][j][c] = 0.f;

#pragma unroll
    for (int ks = 0; ks < 8; ++ks) {
        unsigned bb[4][2];
#pragma unroll
        for (int j = 0; j < 4; ++j) {
            uint2 v = sB[(ks * 8 + half * 4 + j) * 32 + lane];
            bb[j][0] = v.x; bb[j][1] = v.y;
        }
        unsigned aa[3][4];
#pragma unroll
        for (int m = 0; m < 2; ++m) {
            int base = (m * 16 + g) * RS + ks * 8 + t;
            aa[m][0] = sNb[base];
            aa[m][1] = sNb[base + 8 * RS];
            aa[m][2] = sNb[base + 4];
            aa[m][3] = sNb[base + 8 * RS + 4];
        }
        if (g == 0) {   // m-tile 2: only row 32 real
            int base = 32 * RS + ks * 8 + t;
            aa[2][0] = sNb[base];
            aa[2][2] = sNb[base + 4];
        } else { aa[2][0] = 0u; aa[2][2] = 0u; }
        aa[2][1] = 0u; aa[2][3] = 0u;

#pragma unroll
        for (int m = 0; m < 3; ++m)
#pragma unroll
            for (int j = 0; j < 4; ++j)
                MMA_TF32(d[m][j], aa[m], bb[j]);
    }

    // ---- epilogue params (post-GEMM to keep mainloop registers lean) ----
    const int col0 = half * 32 + 2 * t;
    float2 wb2[4], aw2[4], g2[4], be2[4];
#pragma unroll
    for (int j = 0; j < 4; ++j) {
        wb2[j] = *(const float2*)(Wbias + col0 + j * 8);
        aw2[j] = *(const float2*)(attw + 64 + col0 + j * 8);
        g2[j]  = *(const float2*)(gamma + col0 + j * 8);
        be2[j] = *(const float2*)(beta  + col0 + j * 8);
    }

    // ---- add bias; per-row stats (sum, sumsq, score) ----
#pragma unroll
    for (int m = 0; m < 3; ++m)
#pragma unroll
        for (int j = 0; j < 4; ++j) {
            d[m][j][0] += wb2[j].x; d[m][j][1] += wb2[j].y;
            d[m][j][2] += wb2[j].x; d[m][j][3] += wb2[j].y;
        }

    float sm[3][2], s2[3][2], sc[3][2];
#pragma unroll
    for (int m = 0; m < 3; ++m)
#pragma unroll
        for (int rh = 0; rh < 2; ++rh) {
            float a = 0.f, q = 0.f, s = 0.f;
#pragma unroll
            for (int j = 0; j < 4; ++j) {
                float h0 = d[m][j][rh * 2], h1 = d[m][j][rh * 2 + 1];
                a += h0 + h1;
                q = fmaf(h0, h0, fmaf(h1, h1, q));
                s = fmaf(h0, aw2[j].x, fmaf(h1, aw2[j].y, s));
            }
#pragma unroll
            for (int dl = 1; dl <= 2; dl <<= 1) {
                a += __shfl_xor_sync(0xffffffffu, a, dl);
                q += __shfl_xor_sync(0xffffffffu, q, dl);
                s += __shfl_xor_sync(0xffffffffu, s, dl);
            }
            sm[m][rh] = a; s2[m][rh] = q; sc[m][rh] = s;
        }
    if (t == 0) {
        sSum[bl][half][g]      = make_float2(sm[0][0], s2[0][0]);
        sSum[bl][half][g + 8]  = make_float2(sm[0][1], s2[0][1]);
        sSum[bl][half][g + 16] = make_float2(sm[1][0], s2[1][0]);
        sSum[bl][half][g + 24] = make_float2(sm[1][1], s2[1][1]);
        if (g > 0) sScore[bl][half][g - 1] = sc[0][0];
        sScore[bl][half][g + 7]  = sc[0][1];   // row g+8
        sScore[bl][half][g + 15] = sc[1][0];   // row 16+g
        sScore[bl][half][g + 23] = sc[1][1];   // row 24+g
        if (g == 0) {
            sSum[bl][half][32]   = make_float2(sm[2][0], s2[2][0]);
            sScore[bl][half][31] = sc[2][0];   // row 32
        }
    }
    BARX(barid);   // only this batch's 2 warps (sSum/sScore/sEk visible)

    // ---- softmax (both warps redundantly, registers; scores are tiny so
    //      the max-shift is unnecessary: |s| << 80) ----
    float p = __expf(sScore[bl][0][lane] + sScore[bl][1][lane] + sEk[bl][lane]);
    float tot = p;
#pragma unroll
    for (int dl = 16; dl > 0; dl >>= 1) tot += __shfl_xor_sync(0xffffffffu, tot, dl);
    const float attn = p / tot;   // lane k holds attn for neighbor row k+1

    // ---- layernorm + store for neighbor rows (1..32); streaming stores ----
    float* gO = out + b * 2112;
#pragma unroll
    for (int m = 0; m < 3; ++m)
#pragma unroll
        for (int rh = 0; rh < 2; ++rh) {
            int row = m * 16 + g + rh * 8;
            bool valid = (row >= 1) && (row <= 32) && !(m == 2 && !(g == 0 && rh == 0));
            if (valid) {
                float2 u0 = sSum[bl][0][row];
                float2 u1 = sSum[bl][1][row];
                float mu  = (u0.x + u1.x) * (1.f / 64.f);
                float var = fmaf(u0.y + u1.y, 1.f / 64.f, -mu * mu);
                float ri  = rsqrtf(var + EPSLN);
#pragma unroll
                for (int j = 0; j < 4; ++j) {
                    float2 o;
                    o.x = fmaf((d[m][j][rh * 2]     - mu) * ri, g2[j].x, be2[j].x);
                    o.y = fmaf((d[m][j][rh * 2 + 1] - mu) * ri, g2[j].y, be2[j].y);
                    __stcs((float2*)(gO + row * 64 + col0 + j * 8), o);
                }
            }
        }

    // ---- message coefficients via in-register shuffles (no barrier) ----
    float aA = __shfl_sync(0xffffffffu, attn, (g == 0) ? 0 : (g - 1));
    if (g == 0) aA = 0.f;                                  // row g   (g>=1)
    float aB = __shfl_sync(0xffffffffu, attn, g + 7);      // row g+8
    float aC = __shfl_sync(0xffffffffu, attn, g + 15);     // row 16+g
    float aD = __shfl_sync(0xffffffffu, attn, g + 23);     // row 24+g
    float aE = __shfl_sync(0xffffffffu, attn, 31);         // row 32
    if (g != 0) aE = 0.f;

    float pm[4][2];
#pragma unroll
    for (int j = 0; j < 4; ++j)
#pragma unroll
        for (int c = 0; c < 2; ++c) {
            float v = aA * d[0][j][c] + aB * d[0][j][2 + c]
                    + aC * d[1][j][c] + aD * d[1][j][2 + c]
                    + aE * d[2][j][c];
#pragma unroll
            for (int dl = 4; dl <= 16; dl <<= 1)
                v += __shfl_xor_sync(0xffffffffu, v, dl);
            pm[j][c] = v;
        }

    // ---- target row 0 (held by g==0 lanes) ----
    float tv[4][2];
    float tsm = 0.f, ts2 = 0.f;
#pragma unroll
    for (int j = 0; j < 4; ++j)
#pragma unroll
        for (int c = 0; c < 2; ++c) {
            float v = d[0][j][c] + pm[j][c];
            tv[j][c] = v;
            tsm += v;
            ts2 = fmaf(v, v, ts2);
        }
#pragma unroll
    for (int dl = 1; dl <= 2; dl <<= 1) {
        tsm += __shfl_xor_sync(0xffffffffu, tsm, dl);
        ts2 += __shfl_xor_sync(0xffffffffu, ts2, dl);
    }
    if (lane == 0) sT[bl][half] = make_float2(tsm, ts2);
    BARX(barid);

    if (lane < 4) {  // g==0, t=0..3 lanes write target row
        float2 v0 = sT[bl][0], v1 = sT[bl][1];
        float mu  = (v0.x + v1.x) * (1.f / 64.f);
        float var = fmaf(v0.y + v1.y, 1.f / 64.f, -mu * mu);
        float ri  = rsqrtf(var + EPSLN);
#pragma unroll
        for (int j = 0; j < 4; ++j) {
            float2 o;
            o.x = fmaf((tv[j][0] - mu) * ri, g2[j].x, be2[j].x);
            o.y = fmaf((tv[j][1] - mu) * ri, g2[j].y, be2[j].y);
            __stcs((float2*)(gO + col0 + j * 8), o);
        }
    }
}

extern "C" void kernel_launch(void* const* d_in, const int* in_sizes, int n_in,
                              void* d_out, int out_size) {
    const float* nodes = (const float*)d_in[0];
    const float* edges = (const float*)d_in[1];
    const float* Ww    = (const float*)d_in[2];
    const float* Wb    = (const float*)d_in[3];
    const float* Wew   = (const float*)d_in[4];
    // d_in[5] = We_b   (cancels under softmax shift-invariance)
    const float* attw  = (const float*)d_in[6];
    // d_in[7] = attn_b (cancels under softmax shift-invariance)
    const float* gamma = (const float*)d_in[8];
    const float* beta  = (const float*)d_in[9];

    prep_kernel<<<16, 128>>>(Ww, Wew, attw);

    // PDL: gat launches while prep drains; gat blocks only at its
    // cudaGridDependencySynchronize() (after node cp.async issue).
    cudaLaunchConfig_t cfg = {};
    cfg.gridDim  = dim3(16384 / 4);
    cfg.blockDim = dim3(256);
    cfg.dynamicSmemBytes = 0;
    cfg.stream = 0;
    cudaLaunchAttribute attrs[1];
    attrs[0].id = cudaLaunchAttributeProgrammaticStreamSerialization;
    attrs[0].val.programmaticStreamSerializationAllowed = 1;
    cfg.attrs = attrs;
    cfg.numAttrs = 1;
    cudaLaunchKernelEx(&cfg, gat_kernel, nodes, edges, Wb, attw, gamma, beta,
                       (float*)d_out);
}

// round 16
// speedup vs baseline: 1.4081x; 1.2350x over previous
#include <cuda_runtime.h>
#include <cuda_fp16.h>

#define EPSLN 1e-5f
#define RS2 72   // smem row stride in HALFS (word = 36g + 8kc + t -> conflict-free)

// Precomputed per launch (deterministic, graph-capturable)
// fp16 B fragment for m16n8k16.row.col:
//   b0 = {W[16kc+2t][n], W[16kc+2t+1][n]}, b1 = {W[16kc+2t+8][n], W[16kc+2t+9][n]}
__device__ __align__(16) uint2 g_Wfrag[4 * 8 * 32];
__device__ __align__(16) float g_ewproj[16];         // We_w @ attn_w[128:192]

// pack two fp32 -> f16x2 (lo = first arg)  [PTX: d.lo = second src, d.hi = first]
__device__ __forceinline__ unsigned packh2(float lo, float hi) {
    unsigned r; asm("cvt.rn.f16x2.f32 %0, %1, %2;" : "=r"(r) : "f"(hi), "f"(lo));
    return r;
}

#define MMA_F16(d, a, b)                                                           \
    asm volatile(                                                                  \
        "mma.sync.aligned.m16n8k16.row.col.f32.f16.f16.f32 "                       \
        "{%0,%1,%2,%3},{%4,%5,%6,%7},{%8,%9},{%0,%1,%2,%3};"                       \
        : "+f"(d[0]), "+f"(d[1]), "+f"(d[2]), "+f"(d[3])                           \
        : "r"(a[0]), "r"(a[1]), "r"(a[2]), "r"(a[3]), "r"(b[0]), "r"(b[1]))

// Named barrier over the 64 threads (2 warps) serving one batch
#define BARX(id) asm volatile("bar.sync %0, 64;" :: "r"(id) : "memory")

__global__ void prep_kernel(const float* __restrict__ Ww,
                            const float* __restrict__ Wew,
                            const float* __restrict__ attw) {
    int tid = threadIdx.x;  // 128 threads, 8 blocks
    if (blockIdx.x == 0) {
        // ewproj[e] = sum_o Wew[e][o] * attw[128+o]; 8 threads per e
        int e = tid >> 3, sub = tid & 7;
        float p = 0.f;
#pragma unroll
        for (int o = 0; o < 8; ++o)
            p += Wew[e * 64 + sub * 8 + o] * attw[128 + sub * 8 + o];
#pragma unroll
        for (int dl = 1; dl <= 4; dl <<= 1)
            p += __shfl_xor_sync(0xffffffffu, p, dl);
        if (sub == 0) g_ewproj[e] = p;
    }
    int idx = blockIdx.x * 128 + tid;   // 8*128 = 1024 exactly
    {
        int lane = idx & 31;
        int nt   = (idx >> 5) & 7;
        int kc   = idx >> 8;
        int t = lane & 3, g = lane >> 2;
        int n  = nt * 8 + g;
        int k0 = kc * 16 + 2 * t;
        uint2 v;
        v.x = packh2(Ww[(k0)     * 64 + n], Ww[(k0 + 1) * 64 + n]);
        v.y = packh2(Ww[(k0 + 8) * 64 + n], Ww[(k0 + 9) * 64 + n]);
        g_Wfrag[idx] = v;
    }
}

__global__ __launch_bounds__(256, 3) void gat_kernel(
    const float* __restrict__ nodes,
    const float* __restrict__ edges,
    const float* __restrict__ Wbias,
    const float* __restrict__ attw,
    const float* __restrict__ gamma,
    const float* __restrict__ beta,
    float* __restrict__ out)
{
    __shared__ __align__(16) __half sN[4][33 * RS2];  // nodes, fp16 (19 KB)
    __shared__ uint2  sB[4 * 8 * 32];        // fp16 weight fragments (8 KB)
    __shared__ float2 sSum[4][2][33];        // (sum, sumsq) per row/half
    __shared__ float  sScore[4][2][32];      // partial attention scores rows 1..32
    __shared__ float  sEk[4][32];            // edge score terms per neighbor
    __shared__ float2 sT[4][2];              // target LN partials per half

    const int tid  = threadIdx.x;
    const int lane = tid & 31;
    const int warp = tid >> 5;
    const int bl   = warp >> 1;     // batch within CTA (0..3)
    const int half = warp & 1;      // column half (32 cols)
    const int t    = lane & 3;      // threadID-in-group
    const int g    = lane >> 2;     // groupID
    const long long b = (long long)blockIdx.x * 4 + bl;
    const int barid = bl + 1;

    // ---- stage nodes: LDG -> cvt fp16 -> STS (independent of prep; before
    //      the grid-dependency sync so prep overlaps this latency) ----
    const float4* srcAll = (const float4*)(nodes + (long long)blockIdx.x * 4 * 2112);
#pragma unroll
    for (int qq = 0; qq < 9; ++qq) {
        int q = tid + qq * 256;
        if (q < 2112) {
            int bb = q / 528;
            int ql = q - bb * 528;
            int r  = ql >> 4, i4 = ql & 15;
            float4 v = srcAll[q];
            uint2 h;
            h.x = packh2(v.x, v.y);
            h.y = packh2(v.z, v.w);
            *(uint2*)&sN[bb][r * RS2 + i4 * 4] = h;
        }
    }

    // ---- PDL: wait for prep_kernel's g_Wfrag / g_ewproj before reading ----
    cudaGridDependencySynchronize();

    // ---- stage weight fragments (8 KB, once per CTA / 4 batches) ----
#pragma unroll
    for (int k = 0; k < 4; ++k) sB[tid + k * 256] = g_Wfrag[tid + k * 256];

    // ---- edge score term (half==0 warps, lane = neighbor k) ----
    if (half == 0) {
        const float4* er = (const float4*)(edges + (b * 32 + lane) * 16);
        float ek = 0.f;
#pragma unroll
        for (int e4 = 0; e4 < 4; ++e4) {
            float4 a = er[e4];
            float4 w = *(const float4*)&g_ewproj[e4 * 4];
            ek += a.x * w.x + a.y * w.y + a.z * w.z + a.w * w.w;
        }
        sEk[bl][lane] = ek;
    }

    __syncthreads();  // staging complete (CTA-wide, once)

    // ---- tensor-core GEMM: fp16 m16n8k16, 3 m-tiles x 4 n-tiles x 4 k-chunks ----
    const unsigned* sNb = (const unsigned*)sN[bl];   // f16x2 words, row stride 36
    float d[3][4][4];
#pragma unroll
    for (int m = 0; m < 3; ++m)
#pragma unroll
        for (int j = 0; j < 4; ++j)
#pragma unroll
            for (int c = 0; c < 4; ++c) d[m][j][c] = 0.f;

#pragma unroll
    for (int kc = 0; kc < 4; ++kc) {
        unsigned bb[4][2];
#pragma unroll
        for (int j = 0; j < 4; ++j) {
            uint2 v = sB[(kc * 8 + half * 4 + j) * 32 + lane];
            bb[j][0] = v.x; bb[j][1] = v.y;
        }
        unsigned aa[3][4];
#pragma unroll
        for (int m = 0; m < 2; ++m) {
            int base = (m * 16 + g) * 36 + kc * 8 + t;
            aa[m][0] = sNb[base];             // row g,    k = 32kc+2t, +1
            aa[m][1] = sNb[base + 8 * 36];    // row g+8
            aa[m][2] = sNb[base + 4];         // row g,    k + 8
            aa[m][3] = sNb[base + 8 * 36 + 4];
        }
        if (g == 0) {   // m-tile 2: only row 32 real
            int base = 32 * 36 + kc * 8 + t;
            aa[2][0] = sNb[base];
            aa[2][2] = sNb[base + 4];
        } else { aa[2][0] = 0u; aa[2][2] = 0u; }
        aa[2][1] = 0u; aa[2][3] = 0u;

#pragma unroll
        for (int m = 0; m < 3; ++m)
#pragma unroll
            for (int j = 0; j < 4; ++j)
                MMA_F16(d[m][j], aa[m], bb[j]);
    }

    // ---- epilogue params (post-GEMM to keep mainloop registers lean) ----
    const int col0 = half * 32 + 2 * t;
    float2 wb2[4], aw2[4], g2[4], be2[4];
#pragma unroll
    for (int j = 0; j < 4; ++j) {
        wb2[j] = *(const float2*)(Wbias + col0 + j * 8);
        aw2[j] = *(const float2*)(attw + 64 + col0 + j * 8);
        g2[j]  = *(const float2*)(gamma + col0 + j * 8);
        be2[j] = *(const float2*)(beta  + col0 + j * 8);
    }

    // ---- add bias; per-row stats (sum, sumsq, score) ----
#pragma unroll
    for (int m = 0; m < 3; ++m)
#pragma unroll
        for (int j = 0; j < 4; ++j) {
            d[m][j][0] += wb2[j].x; d[m][j][1] += wb2[j].y;
            d[m][j][2] += wb2[j].x; d[m][j][3] += wb2[j].y;
        }

    float sm[3][2], s2[3][2], sc[3][2];
#pragma unroll
    for (int m = 0; m < 3; ++m)
#pragma unroll
        for (int rh = 0; rh < 2; ++rh) {
            float a = 0.f, q = 0.f, s = 0.f;
#pragma unroll
            for (int j = 0; j < 4; ++j) {
                float h0 = d[m][j][rh * 2], h1 = d[m][j][rh * 2 + 1];
                a += h0 + h1;
                q = fmaf(h0, h0, fmaf(h1, h1, q));
                s = fmaf(h0, aw2[j].x, fmaf(h1, aw2[j].y, s));
            }
#pragma unroll
            for (int dl = 1; dl <= 2; dl <<= 1) {
                a += __shfl_xor_sync(0xffffffffu, a, dl);
                q += __shfl_xor_sync(0xffffffffu, q, dl);
                s += __shfl_xor_sync(0xffffffffu, s, dl);
            }
            sm[m][rh] = a; s2[m][rh] = q; sc[m][rh] = s;
        }
    if (t == 0) {
        sSum[bl][half][g]      = make_float2(sm[0][0], s2[0][0]);
        sSum[bl][half][g + 8]  = make_float2(sm[0][1], s2[0][1]);
        sSum[bl][half][g + 16] = make_float2(sm[1][0], s2[1][0]);
        sSum[bl][half][g + 24] = make_float2(sm[1][1], s2[1][1]);
        if (g > 0) sScore[bl][half][g - 1] = sc[0][0];
        sScore[bl][half][g + 7]  = sc[0][1];   // row g+8
        sScore[bl][half][g + 15] = sc[1][0];   // row 16+g
        sScore[bl][half][g + 23] = sc[1][1];   // row 24+g
        if (g == 0) {
            sSum[bl][half][32]   = make_float2(sm[2][0], s2[2][0]);
            sScore[bl][half][31] = sc[2][0];   // row 32
        }
    }
    BARX(barid);   // only this batch's 2 warps (sSum/sScore/sEk visible)

    // ---- softmax (both warps redundantly, registers; scores are tiny so
    //      the max-shift is unnecessary: |s| << 80) ----
    float p = __expf(sScore[bl][0][lane] + sScore[bl][1][lane] + sEk[bl][lane]);
    float tot = p;
#pragma unroll
    for (int dl = 16; dl > 0; dl >>= 1) tot += __shfl_xor_sync(0xffffffffu, tot, dl);
    const float attn = p / tot;   // lane k holds attn for neighbor row k+1

    // ---- layernorm + store for neighbor rows (1..32); streaming stores ----
    float* gO = out + b * 2112;
#pragma unroll
    for (int m = 0; m < 3; ++m)
#pragma unroll
        for (int rh = 0; rh < 2; ++rh) {
            int row = m * 16 + g + rh * 8;
            bool valid = (row >= 1) && (row <= 32) && !(m == 2 && !(g == 0 && rh == 0));
            if (valid) {
                float2 u0 = sSum[bl][0][row];
                float2 u1 = sSum[bl][1][row];
                float mu  = (u0.x + u1.x) * (1.f / 64.f);
                float var = fmaf(u0.y + u1.y, 1.f / 64.f, -mu * mu);
                float ri  = rsqrtf(var + EPSLN);
#pragma unroll
                for (int j = 0; j < 4; ++j) {
                    float2 o;
                    o.x = fmaf((d[m][j][rh * 2]     - mu) * ri, g2[j].x, be2[j].x);
                    o.y = fmaf((d[m][j][rh * 2 + 1] - mu) * ri, g2[j].y, be2[j].y);
                    __stcs((float2*)(gO + row * 64 + col0 + j * 8), o);
                }
            }
        }

    // ---- message coefficients via in-register shuffles (no barrier) ----
    float aA = __shfl_sync(0xffffffffu, attn, (g == 0) ? 0 : (g - 1));
    if (g == 0) aA = 0.f;                                  // row g   (g>=1)
    float aB = __shfl_sync(0xffffffffu, attn, g + 7);      // row g+8
    float aC = __shfl_sync(0xffffffffu, attn, g + 15);     // row 16+g
    float aD = __shfl_sync(0xffffffffu, attn, g + 23);     // row 24+g
    float aE = __shfl_sync(0xffffffffu, attn, 31);         // row 32
    if (g != 0) aE = 0.f;

    float pm[4][2];
#pragma unroll
    for (int j = 0; j < 4; ++j)
#pragma unroll
        for (int c = 0; c < 2; ++c) {
            float v = aA * d[0][j][c] + aB * d[0][j][2 + c]
                    + aC * d[1][j][c] + aD * d[1][j][2 + c]
                    + aE * d[2][j][c];
#pragma unroll
            for (int dl = 4; dl <= 16; dl <<= 1)
                v += __shfl_xor_sync(0xffffffffu, v, dl);
            pm[j][c] = v;
        }

    // ---- target row 0 (held by g==0 lanes) ----
    float tv[4][2];
    float tsm = 0.f, ts2 = 0.f;
#pragma unroll
    for (int j = 0; j < 4; ++j)
#pragma unroll
        for (int c = 0; c < 2; ++c) {
            float v = d[0][j][c] + pm[j][c];
            tv[j][c] = v;
            tsm += v;
            ts2 = fmaf(v, v, ts2);
        }
#pragma unroll
    for (int dl = 1; dl <= 2; dl <<= 1) {
        tsm += __shfl_xor_sync(0xffffffffu, tsm, dl);
        ts2 += __shfl_xor_sync(0xffffffffu, ts2, dl);
    }
    if (lane == 0) sT[bl][half] = make_float2(tsm, ts2);
    BARX(barid);

    if (lane < 4) {  // g==0, t=0..3 lanes write target row
        float2 v0 = sT[bl][0], v1 = sT[bl][1];
        float mu  = (v0.x + v1.x) * (1.f / 64.f);
        float var = fmaf(v0.y + v1.y, 1.f / 64.f, -mu * mu);
        float ri  = rsqrtf(var + EPSLN);
#pragma unroll
        for (int j = 0; j < 4; ++j) {
            float2 o;
            o.x = fmaf((tv[j][0] - mu) * ri, g2[j].x, be2[j].x);
            o.y = fmaf((tv[j][1] - mu) * ri, g2[j].y, be2[j].y);
            __stcs((float2*)(gO + col0 + j * 8), o);
        }
    }
}

extern "C" void kernel_launch(void* const* d_in, const int* in_sizes, int n_in,
                              void* d_out, int out_size) {
    const float* nodes = (const float*)d_in[0];
    const float* edges = (const float*)d_in[1];
    const float* Ww    = (const float*)d_in[2];
    const float* Wb    = (const float*)d_in[3];
    const float* Wew   = (const float*)d_in[4];
    // d_in[5] = We_b   (cancels under softmax shift-invariance)
    const float* attw  = (const float*)d_in[6];
    // d_in[7] = attn_b (cancels under softmax shift-invariance)
    const float* gamma = (const float*)d_in[8];
    const float* beta  = (const float*)d_in[9];

    prep_kernel<<<8, 128>>>(Ww, Wew, attw);

    // PDL: gat launches while prep drains; gat blocks only at its
    // cudaGridDependencySynchronize() (after node staging LDGs issue).
    cudaLaunchConfig_t cfg = {};
    cfg.gridDim  = dim3(16384 / 4);
    cfg.blockDim = dim3(256);
    cfg.dynamicSmemBytes = 0;
    cfg.stream = 0;
    cudaLaunchAttribute attrs[1];
    attrs[0].id = cudaLaunchAttributeProgrammaticStreamSerialization;
    attrs[0].val.programmaticStreamSerializationAllowed = 1;
    cfg.attrs = attrs;
    cfg.numAttrs = 1;
    cudaLaunchKernelEx(&cfg, gat_kernel, nodes, edges, Wb, attw, gamma, beta,
                       (float*)d_out);
}